// round 15
// baseline (speedup 1.0000x reference)
#include <cuda_runtime.h>
#include <cuda_bf16.h>
#include <cuda_fp16.h>
#include <math.h>
#include <stdint.h>

#define Bd   8
#define Hd   1024
#define Ld   2048
#define Cd   2
#define NF   4096      // FFT length = 2L
#define CH   2048      // C*H (GEMM K)
#define OUTD 2048      // 2H  (GEMM M, interleaved a/g rows)

// ---------------- scratch (static device globals; no runtime allocation) ----
__device__ float2 d_kf[(size_t)CH * NF];            // kernel spectra
__device__ int    d_kf_nz[CH];                      // per-row nonzero flags
__device__ __half d_g_h[(size_t)Bd * CH * Ld];      // post-GELU activations fp16 (k-major)
__device__ __half d_W_h[(size_t)OUTD * CH];         // W fp16, rows permuted for fused GLU

__device__ __forceinline__ float2 cmulf(float2 a, float2 b) {
    return make_float2(a.x * b.x - a.y * b.y, a.x * b.y + a.y * b.x);
}
__device__ __forceinline__ float gelu_f(float y) {
    return 0.5f * y * (1.0f + erff(y * 0.70710678118654752f));
}

// ---------------------------------------------------------------------------
// Stockham radix-2 FFT, N=4096, 256 threads/block.
// ---------------------------------------------------------------------------
template<int SIGN>
__device__ void fft4096(float2* a, float2* b) {
    float2 *s = a, *d = b;
    int Ns = 1;
    #pragma unroll 1
    for (int stage = 0; stage < 12; ++stage) {
        __syncthreads();
        float wstep = (float)SIGN * 3.14159265358979323846f / (float)Ns;
        #pragma unroll
        for (int it = 0; it < 8; ++it) {
            int j = threadIdx.x + (it << 8);
            float2 v0 = s[j];
            float2 v1 = s[j + 2048];
            int jm = j & (Ns - 1);
            float ang = wstep * (float)jm;
            float sn, cs;
            __sincosf(ang, &sn, &cs);
            float2 t = make_float2(cs * v1.x - sn * v1.y,
                                   cs * v1.y + sn * v1.x);
            int idxD = 2 * j - jm;
            d[idxD]      = make_float2(v0.x + t.x, v0.y + t.y);
            d[idxD + Ns] = make_float2(v0.x - t.x, v0.y - t.y);
        }
        float2* tmp = s; s = d; d = tmp;
        Ns <<= 1;
    }
    __syncthreads();
}

// ---------------------------------------------------------------------------
// Kernel 0: flags only — any |kern[row][i]| > lam?  No smem FFT, fast.
// ---------------------------------------------------------------------------
__global__ void flag_kernel(const float* __restrict__ kern) {
    __shared__ int s_any;
    if (threadIdx.x == 0) s_any = 0;
    __syncthreads();
    int row = blockIdx.x;
    const float4* kr = reinterpret_cast<const float4*>(kern + (size_t)row * NF);
    int any = 0;
    #pragma unroll
    for (int i = 0; i < 4; ++i) {
        float4 v = kr[threadIdx.x + (i << 8)];
        any |= (fabsf(v.x) > 0.1f) | (fabsf(v.y) > 0.1f) |
               (fabsf(v.z) > 0.1f) | (fabsf(v.w) > 0.1f);
    }
    if (any) s_any = 1;
    __syncthreads();
    if (threadIdx.x == 0) d_kf_nz[row] = s_any;
}

// ---------------------------------------------------------------------------
// Kernel 1: FFT of soft-thresholded filter rows (only nonzero rows).
// ---------------------------------------------------------------------------
__global__ void kf_fft_kernel(const float* __restrict__ kern) {
    int row = blockIdx.x;
    if (!d_kf_nz[row]) return;
    extern __shared__ float2 sm[];
    float2* A  = sm;
    float2* Bf = sm + NF;
    const float* kr = kern + (size_t)row * NF;
    for (int i = threadIdx.x; i < NF; i += 256) {
        float v = kr[i];
        float t = fmaxf(fabsf(v) - 0.1f, 0.0f);
        A[i] = make_float2(copysignf(t, v), 0.0f);
    }
    fft4096<-1>(A, Bf);
    float2* out = d_kf + (size_t)row * NF;
    for (int i = threadIdx.x; i < NF; i += 256) out[i] = A[i];
}

// ---------------------------------------------------------------------------
// Kernel 2a: streaming fast path (both filter rows zero): gelu(u*D) -> fp16.
// Processes 4 batches starting at b0; 8 floats/thread.
// ---------------------------------------------------------------------------
__global__ void ew_kernel(const float* __restrict__ u,
                          const float* __restrict__ Dp, int b0) {
    int idx = blockIdx.x * blockDim.x + threadIdx.x;   // over 4*H*L/8 = 2^20
    int l8 = idx & (Ld / 8 - 1);
    int h  = (idx >> 8) & (Hd - 1);
    int b  = b0 + (idx >> 18);
    if (d_kf_nz[h] | d_kf_nz[Hd + h]) return;          // conv_kernel handles
    const float4* up = reinterpret_cast<const float4*>(
        u + ((size_t)b * Hd + h) * Ld + l8 * 8);
    float4 v0 = up[0], v1 = up[1];
    float D0 = Dp[h], D1 = Dp[Hd + h];
    uint4 o0, o1;
    {
        __half2 a = __floats2half2_rn(gelu_f(v0.x * D0), gelu_f(v0.y * D0));
        __half2 b2 = __floats2half2_rn(gelu_f(v0.z * D0), gelu_f(v0.w * D0));
        __half2 c = __floats2half2_rn(gelu_f(v1.x * D0), gelu_f(v1.y * D0));
        __half2 d = __floats2half2_rn(gelu_f(v1.z * D0), gelu_f(v1.w * D0));
        o0.x = *reinterpret_cast<uint32_t*>(&a);
        o0.y = *reinterpret_cast<uint32_t*>(&b2);
        o0.z = *reinterpret_cast<uint32_t*>(&c);
        o0.w = *reinterpret_cast<uint32_t*>(&d);
    }
    {
        __half2 a = __floats2half2_rn(gelu_f(v0.x * D1), gelu_f(v0.y * D1));
        __half2 b2 = __floats2half2_rn(gelu_f(v0.z * D1), gelu_f(v0.w * D1));
        __half2 c = __floats2half2_rn(gelu_f(v1.x * D1), gelu_f(v1.y * D1));
        __half2 d = __floats2half2_rn(gelu_f(v1.z * D1), gelu_f(v1.w * D1));
        o1.x = *reinterpret_cast<uint32_t*>(&a);
        o1.y = *reinterpret_cast<uint32_t*>(&b2);
        o1.z = *reinterpret_cast<uint32_t*>(&c);
        o1.w = *reinterpret_cast<uint32_t*>(&d);
    }
    *reinterpret_cast<uint4*>(d_g_h + ((size_t)b * CH + h) * Ld + l8 * 8) = o0;
    *reinterpret_cast<uint4*>(d_g_h + ((size_t)b * CH + Hd + h) * Ld + l8 * 8) = o1;
}

// ---------------------------------------------------------------------------
// Kernel 2b: FFT conv path — persistent grid; work only for nonzero rows.
// ---------------------------------------------------------------------------
__global__ void conv_kernel(const float* __restrict__ u,
                            const float* __restrict__ Dp) {
    extern __shared__ float2 sm[];
    float2* A  = sm;
    float2* Bf = sm + NF;
    float2* Uf = sm + 2 * NF;
    __half* stg = reinterpret_cast<__half*>(Bf);
    #pragma unroll 1
    for (int bh = blockIdx.x; bh < Bd * Hd; bh += gridDim.x) {
        int b = bh >> 10;
        int h = bh & (Hd - 1);
        int nz0 = d_kf_nz[h];
        int nz1 = d_kf_nz[Hd + h];
        if (!(nz0 | nz1)) continue;                    // ew_kernel handled
        __syncthreads();                               // smem reuse guard
        const float* ur = u + ((size_t)b * Hd + h) * Ld;
        float ul[8];
        #pragma unroll
        for (int it = 0; it < 8; ++it) {
            int l = threadIdx.x + (it << 8);
            float v = ur[l];
            ul[it] = v;
            A[l]      = make_float2(v, 0.0f);
            A[l + Ld] = make_float2(0.0f, 0.0f);
        }
        fft4096<-1>(A, Bf);
        for (int i = threadIdx.x; i < NF; i += 256) Uf[i] = A[i];
        __syncthreads();
        #pragma unroll 1
        for (int c = 0; c < Cd; ++c) {
            int nz = c ? nz1 : nz0;
            float Dch = Dp[c * Hd + h];
            __half* gr = d_g_h + ((size_t)b * CH + (size_t)c * Hd + h) * Ld;
            if (nz) {
                __syncthreads();
                const float2* kfr = d_kf + ((size_t)c * Hd + h) * NF;
                for (int i = threadIdx.x; i < NF; i += 256)
                    A[i] = cmulf(Uf[i], kfr[i]);
                fft4096<1>(A, Bf);
                #pragma unroll
                for (int it = 0; it < 8; ++it) {
                    int l = threadIdx.x + (it << 8);
                    float y = A[l].x * (1.0f / (float)NF) + ul[it] * Dch;
                    stg[l] = __float2half(gelu_f(y));
                }
            } else {
                __syncthreads();
                #pragma unroll
                for (int it = 0; it < 8; ++it) {
                    int l = threadIdx.x + (it << 8);
                    stg[l] = __float2half(gelu_f(ul[it] * Dch));
                }
            }
            __syncthreads();
            reinterpret_cast<uint4*>(gr)[threadIdx.x] =
                reinterpret_cast<const uint4*>(stg)[threadIdx.x];
        }
    }
}

// ---------------------------------------------------------------------------
// Kernel 3: W fp32 -> fp16 with GLU-fused row permutation, vectorized 8/thread.
// ---------------------------------------------------------------------------
__global__ void whalf_kernel(const float* __restrict__ W) {
    int idx = blockIdx.x * blockDim.x + threadIdx.x;   // over OUTD*CH/8
    if (idx >= OUTD * CH / 8) return;
    int r  = idx >> 8;                 // / (CH/8)
    int k8 = idx & (CH / 8 - 1);
    int grp = r >> 4, w = r & 15;
    int h = grp * 8 + (w & 7);
    int orig = (w < 8) ? h : h + Hd;
    const float4* src = reinterpret_cast<const float4*>(
        W + (size_t)orig * CH + k8 * 8);
    float4 v0 = src[0], v1 = src[1];
    __half2 h0 = __floats2half2_rn(v0.x, v0.y);
    __half2 h1 = __floats2half2_rn(v0.z, v0.w);
    __half2 h2 = __floats2half2_rn(v1.x, v1.y);
    __half2 h3 = __floats2half2_rn(v1.z, v1.w);
    uint4 o;
    o.x = *reinterpret_cast<uint32_t*>(&h0);
    o.y = *reinterpret_cast<uint32_t*>(&h1);
    o.z = *reinterpret_cast<uint32_t*>(&h2);
    o.w = *reinterpret_cast<uint32_t*>(&h3);
    *reinterpret_cast<uint4*>(d_W_h + (size_t)r * CH + k8 * 8) = o;
}

// ---------------------------------------------------------------------------
// HMMA GEMM helpers
// ---------------------------------------------------------------------------
__device__ __forceinline__ uint32_t smem_u32(const void* p) {
    uint32_t a;
    asm("{ .reg .u64 t; cvta.to.shared.u64 t, %1; cvt.u32.u64 %0, t; }"
        : "=r"(a) : "l"(p));
    return a;
}
#define SWZ128(x) ((x) ^ (((x) >> 3) & 0x70))
__device__ __forceinline__ void cp16(uint32_t dst, const void* src) {
    asm volatile("cp.async.cg.shared.global [%0], [%1], 16;"
                 :: "r"(dst), "l"(src) : "memory");
}
__device__ __forceinline__ void ldsm4(uint32_t* r, uint32_t addr) {
    asm volatile("ldmatrix.sync.aligned.m8n8.x4.shared.b16 {%0,%1,%2,%3}, [%4];"
                 : "=r"(r[0]), "=r"(r[1]), "=r"(r[2]), "=r"(r[3]) : "r"(addr));
}
__device__ __forceinline__ void ldsm4t(uint32_t* r, uint32_t addr) {
    asm volatile("ldmatrix.sync.aligned.m8n8.x4.trans.shared.b16 {%0,%1,%2,%3}, [%4];"
                 : "=r"(r[0]), "=r"(r[1]), "=r"(r[2]), "=r"(r[3]) : "r"(addr));
}
__device__ __forceinline__ void mma16816(float* c, const uint32_t* a,
                                         uint32_t b0, uint32_t b1) {
    asm volatile(
        "mma.sync.aligned.m16n8k16.row.col.f32.f16.f16.f32 "
        "{%0,%1,%2,%3}, {%4,%5,%6,%7}, {%8,%9}, {%0,%1,%2,%3};"
        : "+f"(c[0]), "+f"(c[1]), "+f"(c[2]), "+f"(c[3])
        : "r"(a[0]), "r"(a[1]), "r"(a[2]), "r"(a[3]), "r"(b0), "r"(b1));
}

// Tile 128(o) x 128(l), K-chunk 64.
// Stage: A 128x128B (SW128) = 16KB ; B 64(k) x 256B (l-major) = 16KB => 32KB
#define STAGE_B   32768
#define B_OFF     16384
#define NSTAGE    2
#define GEMM_SMEM (NSTAGE * STAGE_B)   // 64 KB -> 3 CTAs/SM
#define GTHREADS  128

// B smem phys offset for (k, l): 256B rows, 16B-XOR swizzle within 128B seg
__device__ __forceinline__ uint32_t bswz(int k, int l) {
    return (uint32_t)(k * 256 + ((l >> 6) << 7) + (((l & 63) * 2) ^ ((k & 7) << 4)));
}

__device__ __forceinline__ void load_stage(uint32_t base, int kc, int tid,
                                           const __half* Ap, const __half* Bp) {
    int k0 = kc * 64;
    #pragma unroll
    for (int i = 0; i < 8; ++i) {          // A: 1024 x 16B
        int c = tid + (i << 7);
        int row = c >> 3, col = c & 7;
        cp16(base + SWZ128(row * 128 + col * 16),
             Ap + (size_t)row * CH + k0 + col * 8);
    }
    #pragma unroll
    for (int i = 0; i < 8; ++i) {          // B: 64 rows x 16 chunks of 16B
        int c = tid + (i << 7);
        int row = c >> 4, ch = c & 15;
        cp16(base + B_OFF + bswz(row, ch * 8),
             Bp + (size_t)(k0 + row) * Ld + ch * 8);
    }
    asm volatile("cp.async.commit_group;" ::: "memory");
}

// ---------------------------------------------------------------------------
// Kernel 4: fp16 HMMA GEMM + fused bias/GLU epilogue.
// 128 threads, 4 warps of 64(m) x 64(n), tile 128x128, 2-stage double buffer,
// two barriers per K-chunk, 3 CTAs/SM (launch_bounds cap 170 regs; inner loop
// restructured to ~20 live fragment regs so no spill).
// Co-residency (R11 evidence) hides the barrier + load-latency exposure.
// ---------------------------------------------------------------------------
__global__ void __launch_bounds__(GTHREADS, 3) gemm_hmma(const float* __restrict__ bias,
                                                         float* __restrict__ out,
                                                         int b0) {
    extern __shared__ char smem[];
    uint32_t sb = smem_u32(smem);
    const int tid = threadIdx.x, lane = tid & 31, wid = tid >> 5;
    const int b  = b0 + blockIdx.z;
    const int o0 = blockIdx.y * 128;       // permuted-M tile
    const int l0 = blockIdx.x * 128;
    const int wm = (wid & 1) * 64;         // 2 warp-rows of 64
    const int wn = (wid >> 1) * 64;        // 2 warp-cols of 64

    const __half* Ap = d_W_h + (size_t)o0 * CH;
    const __half* Bp = d_g_h + (size_t)b * CH * Ld + l0;

    float acc[4][8][4];
    #pragma unroll
    for (int mi = 0; mi < 4; ++mi)
        #pragma unroll
        for (int ni = 0; ni < 8; ++ni)
            #pragma unroll
            for (int v = 0; v < 4; ++v) acc[mi][ni][v] = 0.0f;

    load_stage(sb, 0, tid, Ap, Bp);
    load_stage(sb + STAGE_B, 1, tid, Ap, Bp);

    const int arow = (lane & 15);
    const int acol = (lane >> 4) << 4;
    const int bk = (lane & 7) + (lane & 8);
    const int bn = (lane & 16) >> 1;

    #pragma unroll 1
    for (int kc = 0; kc < 32; ++kc) {
        uint32_t base = sb + (kc & 1) * STAGE_B;
        if (kc <= 30) asm volatile("cp.async.wait_group 1;" ::: "memory");
        else          asm volatile("cp.async.wait_group 0;" ::: "memory");
        __syncthreads();
        #pragma unroll
        for (int ks = 0; ks < 4; ++ks) {
            uint32_t a[4][4];
            #pragma unroll
            for (int mi = 0; mi < 4; ++mi)
                ldsm4(a[mi], base + SWZ128((wm + mi * 16 + arow) * 128 +
                                           ks * 32 + acol));
            #pragma unroll
            for (int nj = 0; nj < 4; ++nj) {
                uint32_t bf[4];
                ldsm4t(bf, base + B_OFF + bswz(ks * 16 + bk,
                                               wn + nj * 16 + bn));
                #pragma unroll
                for (int mi = 0; mi < 4; ++mi) {
                    mma16816(acc[mi][2 * nj],     a[mi], bf[0], bf[1]);
                    mma16816(acc[mi][2 * nj + 1], a[mi], bf[2], bf[3]);
                }
            }
        }
        __syncthreads();                   // all warps done with this stage
        if (kc + 2 < 32)
            load_stage(base, kc + 2, tid, Ap, Bp);
    }

    // fused epilogue: a=c0,c1 (rows 0-7), gate=c2,c3 (rows 8-15), same h
    #pragma unroll
    for (int mi = 0; mi < 4; ++mi) {
        int g16 = (o0 + wm + mi * 16) >> 4;
        int h = g16 * 8 + (lane >> 2);
        float ba = bias[h];
        float bg = bias[h + Hd];
        float* orow = out + ((size_t)b * Hd + h) * Ld + l0 + wn;
        #pragma unroll
        for (int ni = 0; ni < 8; ++ni) {
            int lc = ni * 8 + (lane & 3) * 2;
            float a0 = acc[mi][ni][0] + ba;
            float a1 = acc[mi][ni][1] + ba;
            float g0 = acc[mi][ni][2] + bg;
            float g1 = acc[mi][ni][3] + bg;
            float2 v = make_float2(a0 / (1.0f + expf(-g0)),
                                   a1 / (1.0f + expf(-g1)));
            *reinterpret_cast<float2*>(orow + lc) = v;
        }
    }
}

// ---------------------------------------------------------------------------
extern "C" void kernel_launch(void* const* d_in, const int* in_sizes, int n_in,
                              void* d_out, int out_size) {
    const float* u    = (const float*)d_in[0];
    const float* kern = (const float*)d_in[1];
    const float* D    = (const float*)d_in[2];
    const float* Wout = (const float*)d_in[3];
    const float* bout = (const float*)d_in[4];
    float* out = (float*)d_out;

    // streams/events created ONCE on the first (correctness) call — before the
    // harness's pre-capture baseline — and reused afterwards. TWO side streams
    // total (the graph footprint proven safe in R10-R12/R14).
    static cudaStream_t s2 = nullptr, s3 = nullptr;
    static cudaEvent_t eS = nullptr, eW = nullptr, eF = nullptr, eC = nullptr,
                       eG1 = nullptr;
    if (!s2) {
        cudaStreamCreateWithFlags(&s2, cudaStreamNonBlocking);
        cudaStreamCreateWithFlags(&s3, cudaStreamNonBlocking);
        cudaEventCreateWithFlags(&eS,  cudaEventDisableTiming);
        cudaEventCreateWithFlags(&eW,  cudaEventDisableTiming);
        cudaEventCreateWithFlags(&eF,  cudaEventDisableTiming);
        cudaEventCreateWithFlags(&eC,  cudaEventDisableTiming);
        cudaEventCreateWithFlags(&eG1, cudaEventDisableTiming);
        cudaFuncSetAttribute(kf_fft_kernel,
            cudaFuncAttributeMaxDynamicSharedMemorySize, 2 * NF * (int)sizeof(float2));
        cudaFuncSetAttribute(conv_kernel,
            cudaFuncAttributeMaxDynamicSharedMemorySize, 3 * NF * (int)sizeof(float2));
        cudaFuncSetAttribute(gemm_hmma,
            cudaFuncAttributeMaxDynamicSharedMemorySize, GEMM_SMEM);
    }

    // DAG (3 streams total):
    //   0 : flag(eF) -> ew_half0 -> [eW,eC] gemm_half0 -> [eG1]
    //   s2: [eS] whalf(eW) -> [eF] ew_half1 -> [eC] gemm_half1(eG1)
    //   s3: [eF] kf_fft -> conv(eC)
    cudaEventRecord(eS, 0);
    cudaStreamWaitEvent(s2, eS, 0);
    whalf_kernel<<<(OUTD * CH / 8 + 255) / 256, 256, 0, s2>>>(Wout);
    cudaEventRecord(eW, s2);

    flag_kernel<<<CH, 256>>>(kern);
    cudaEventRecord(eF, 0);

    cudaStreamWaitEvent(s3, eF, 0);
    kf_fft_kernel<<<CH, 256, 2 * NF * sizeof(float2), s3>>>(kern);
    conv_kernel<<<296, 256, 3 * NF * sizeof(float2), s3>>>(u, D);
    cudaEventRecord(eC, s3);

    cudaStreamWaitEvent(s2, eF, 0);
    ew_kernel<<<4096, 256, 0, s2>>>(u, D, 4);          // batches 4-7
    cudaStreamWaitEvent(s2, eC, 0);
    gemm_hmma<<<dim3(Ld / 128, OUTD / 128, 4), GTHREADS, GEMM_SMEM, s2>>>(bout, out, 4);
    cudaEventRecord(eG1, s2);

    ew_kernel<<<4096, 256>>>(u, D, 0);                 // batches 0-3 (stream 0)

    cudaStreamWaitEvent(0, eW, 0);
    cudaStreamWaitEvent(0, eC, 0);
    gemm_hmma<<<dim3(Ld / 128, OUTD / 128, 4), GTHREADS, GEMM_SMEM>>>(bout, out, 0);

    cudaStreamWaitEvent(0, eG1, 0);
}

// round 16
// speedup vs baseline: 1.6477x; 1.6477x over previous
#include <cuda_runtime.h>
#include <cuda_bf16.h>
#include <cuda_fp16.h>
#include <math.h>
#include <stdint.h>

#define Bd   8
#define Hd   1024
#define Ld   2048
#define Cd   2
#define NF   4096      // FFT length = 2L
#define CH   2048      // C*H (GEMM K)
#define OUTD 2048      // 2H  (GEMM M, interleaved a/g rows)

// ---------------- scratch (static device globals; no runtime allocation) ----
__device__ float2 d_kf[(size_t)CH * NF];            // kernel spectra
__device__ int    d_kf_nz[CH];                      // per-row nonzero flags
__device__ __half d_g_h[(size_t)Bd * CH * Ld];      // post-GELU activations fp16 (k-major)
__device__ __half d_W_h[(size_t)OUTD * CH];         // W fp16, rows permuted for fused GLU

__device__ __forceinline__ float2 cmulf(float2 a, float2 b) {
    return make_float2(a.x * b.x - a.y * b.y, a.x * b.y + a.y * b.x);
}
__device__ __forceinline__ float gelu_f(float y) {
    return 0.5f * y * (1.0f + erff(y * 0.70710678118654752f));
}

// ---------------------------------------------------------------------------
// Stockham radix-2 FFT, N=4096, 256 threads/block.
// ---------------------------------------------------------------------------
template<int SIGN>
__device__ void fft4096(float2* a, float2* b) {
    float2 *s = a, *d = b;
    int Ns = 1;
    #pragma unroll 1
    for (int stage = 0; stage < 12; ++stage) {
        __syncthreads();
        float wstep = (float)SIGN * 3.14159265358979323846f / (float)Ns;
        #pragma unroll
        for (int it = 0; it < 8; ++it) {
            int j = threadIdx.x + (it << 8);
            float2 v0 = s[j];
            float2 v1 = s[j + 2048];
            int jm = j & (Ns - 1);
            float ang = wstep * (float)jm;
            float sn, cs;
            __sincosf(ang, &sn, &cs);
            float2 t = make_float2(cs * v1.x - sn * v1.y,
                                   cs * v1.y + sn * v1.x);
            int idxD = 2 * j - jm;
            d[idxD]      = make_float2(v0.x + t.x, v0.y + t.y);
            d[idxD + Ns] = make_float2(v0.x - t.x, v0.y - t.y);
        }
        float2* tmp = s; s = d; d = tmp;
        Ns <<= 1;
    }
    __syncthreads();
}

// ---------------------------------------------------------------------------
// Kernel 0: flags only — any |kern[row][i]| > lam?  No smem FFT, fast.
// ---------------------------------------------------------------------------
__global__ void flag_kernel(const float* __restrict__ kern) {
    __shared__ int s_any;
    if (threadIdx.x == 0) s_any = 0;
    __syncthreads();
    int row = blockIdx.x;
    const float4* kr = reinterpret_cast<const float4*>(kern + (size_t)row * NF);
    int any = 0;
    #pragma unroll
    for (int i = 0; i < 4; ++i) {
        float4 v = kr[threadIdx.x + (i << 8)];
        any |= (fabsf(v.x) > 0.1f) | (fabsf(v.y) > 0.1f) |
               (fabsf(v.z) > 0.1f) | (fabsf(v.w) > 0.1f);
    }
    if (any) s_any = 1;
    __syncthreads();
    if (threadIdx.x == 0) d_kf_nz[row] = s_any;
}

// ---------------------------------------------------------------------------
// Kernel 1: FFT of soft-thresholded filter rows (only nonzero rows).
// ---------------------------------------------------------------------------
__global__ void kf_fft_kernel(const float* __restrict__ kern) {
    int row = blockIdx.x;
    if (!d_kf_nz[row]) return;
    extern __shared__ float2 sm[];
    float2* A  = sm;
    float2* Bf = sm + NF;
    const float* kr = kern + (size_t)row * NF;
    for (int i = threadIdx.x; i < NF; i += 256) {
        float v = kr[i];
        float t = fmaxf(fabsf(v) - 0.1f, 0.0f);
        A[i] = make_float2(copysignf(t, v), 0.0f);
    }
    fft4096<-1>(A, Bf);
    float2* out = d_kf + (size_t)row * NF;
    for (int i = threadIdx.x; i < NF; i += 256) out[i] = A[i];
}

// ---------------------------------------------------------------------------
// Kernel 2a: streaming fast path (both filter rows zero): gelu(u*D) -> fp16.
// Processes 4 batches starting at b0; 8 floats/thread.
// ---------------------------------------------------------------------------
__global__ void ew_kernel(const float* __restrict__ u,
                          const float* __restrict__ Dp, int b0) {
    int idx = blockIdx.x * blockDim.x + threadIdx.x;   // over 4*H*L/8 = 2^20
    int l8 = idx & (Ld / 8 - 1);
    int h  = (idx >> 8) & (Hd - 1);
    int b  = b0 + (idx >> 18);
    if (d_kf_nz[h] | d_kf_nz[Hd + h]) return;          // conv_kernel handles
    const float4* up = reinterpret_cast<const float4*>(
        u + ((size_t)b * Hd + h) * Ld + l8 * 8);
    float4 v0 = up[0], v1 = up[1];
    float D0 = Dp[h], D1 = Dp[Hd + h];
    uint4 o0, o1;
    {
        __half2 a = __floats2half2_rn(gelu_f(v0.x * D0), gelu_f(v0.y * D0));
        __half2 b2 = __floats2half2_rn(gelu_f(v0.z * D0), gelu_f(v0.w * D0));
        __half2 c = __floats2half2_rn(gelu_f(v1.x * D0), gelu_f(v1.y * D0));
        __half2 d = __floats2half2_rn(gelu_f(v1.z * D0), gelu_f(v1.w * D0));
        o0.x = *reinterpret_cast<uint32_t*>(&a);
        o0.y = *reinterpret_cast<uint32_t*>(&b2);
        o0.z = *reinterpret_cast<uint32_t*>(&c);
        o0.w = *reinterpret_cast<uint32_t*>(&d);
    }
    {
        __half2 a = __floats2half2_rn(gelu_f(v0.x * D1), gelu_f(v0.y * D1));
        __half2 b2 = __floats2half2_rn(gelu_f(v0.z * D1), gelu_f(v0.w * D1));
        __half2 c = __floats2half2_rn(gelu_f(v1.x * D1), gelu_f(v1.y * D1));
        __half2 d = __floats2half2_rn(gelu_f(v1.z * D1), gelu_f(v1.w * D1));
        o1.x = *reinterpret_cast<uint32_t*>(&a);
        o1.y = *reinterpret_cast<uint32_t*>(&b2);
        o1.z = *reinterpret_cast<uint32_t*>(&c);
        o1.w = *reinterpret_cast<uint32_t*>(&d);
    }
    *reinterpret_cast<uint4*>(d_g_h + ((size_t)b * CH + h) * Ld + l8 * 8) = o0;
    *reinterpret_cast<uint4*>(d_g_h + ((size_t)b * CH + Hd + h) * Ld + l8 * 8) = o1;
}

// ---------------------------------------------------------------------------
// Kernel 2b: FFT conv path — persistent grid; work only for nonzero rows.
// ---------------------------------------------------------------------------
__global__ void conv_kernel(const float* __restrict__ u,
                            const float* __restrict__ Dp) {
    extern __shared__ float2 sm[];
    float2* A  = sm;
    float2* Bf = sm + NF;
    float2* Uf = sm + 2 * NF;
    __half* stg = reinterpret_cast<__half*>(Bf);
    #pragma unroll 1
    for (int bh = blockIdx.x; bh < Bd * Hd; bh += gridDim.x) {
        int b = bh >> 10;
        int h = bh & (Hd - 1);
        int nz0 = d_kf_nz[h];
        int nz1 = d_kf_nz[Hd + h];
        if (!(nz0 | nz1)) continue;                    // ew_kernel handled
        __syncthreads();                               // smem reuse guard
        const float* ur = u + ((size_t)b * Hd + h) * Ld;
        float ul[8];
        #pragma unroll
        for (int it = 0; it < 8; ++it) {
            int l = threadIdx.x + (it << 8);
            float v = ur[l];
            ul[it] = v;
            A[l]      = make_float2(v, 0.0f);
            A[l + Ld] = make_float2(0.0f, 0.0f);
        }
        fft4096<-1>(A, Bf);
        for (int i = threadIdx.x; i < NF; i += 256) Uf[i] = A[i];
        __syncthreads();
        #pragma unroll 1
        for (int c = 0; c < Cd; ++c) {
            int nz = c ? nz1 : nz0;
            float Dch = Dp[c * Hd + h];
            __half* gr = d_g_h + ((size_t)b * CH + (size_t)c * Hd + h) * Ld;
            if (nz) {
                __syncthreads();
                const float2* kfr = d_kf + ((size_t)c * Hd + h) * NF;
                for (int i = threadIdx.x; i < NF; i += 256)
                    A[i] = cmulf(Uf[i], kfr[i]);
                fft4096<1>(A, Bf);
                #pragma unroll
                for (int it = 0; it < 8; ++it) {
                    int l = threadIdx.x + (it << 8);
                    float y = A[l].x * (1.0f / (float)NF) + ul[it] * Dch;
                    stg[l] = __float2half(gelu_f(y));
                }
            } else {
                __syncthreads();
                #pragma unroll
                for (int it = 0; it < 8; ++it) {
                    int l = threadIdx.x + (it << 8);
                    stg[l] = __float2half(gelu_f(ul[it] * Dch));
                }
            }
            __syncthreads();
            reinterpret_cast<uint4*>(gr)[threadIdx.x] =
                reinterpret_cast<const uint4*>(stg)[threadIdx.x];
        }
    }
}

// ---------------------------------------------------------------------------
// Kernel 3: W fp32 -> fp16 with GLU-fused row permutation, vectorized 8/thread.
// ---------------------------------------------------------------------------
__global__ void whalf_kernel(const float* __restrict__ W) {
    int idx = blockIdx.x * blockDim.x + threadIdx.x;   // over OUTD*CH/8
    if (idx >= OUTD * CH / 8) return;
    int r  = idx >> 8;                 // / (CH/8)
    int k8 = idx & (CH / 8 - 1);
    int grp = r >> 4, w = r & 15;
    int h = grp * 8 + (w & 7);
    int orig = (w < 8) ? h : h + Hd;
    const float4* src = reinterpret_cast<const float4*>(
        W + (size_t)orig * CH + k8 * 8);
    float4 v0 = src[0], v1 = src[1];
    __half2 h0 = __floats2half2_rn(v0.x, v0.y);
    __half2 h1 = __floats2half2_rn(v0.z, v0.w);
    __half2 h2 = __floats2half2_rn(v1.x, v1.y);
    __half2 h3 = __floats2half2_rn(v1.z, v1.w);
    uint4 o;
    o.x = *reinterpret_cast<uint32_t*>(&h0);
    o.y = *reinterpret_cast<uint32_t*>(&h1);
    o.z = *reinterpret_cast<uint32_t*>(&h2);
    o.w = *reinterpret_cast<uint32_t*>(&h3);
    *reinterpret_cast<uint4*>(d_W_h + (size_t)r * CH + k8 * 8) = o;
}

// ---------------------------------------------------------------------------
// HMMA GEMM helpers
// ---------------------------------------------------------------------------
__device__ __forceinline__ uint32_t smem_u32(const void* p) {
    uint32_t a;
    asm("{ .reg .u64 t; cvta.to.shared.u64 t, %1; cvt.u32.u64 %0, t; }"
        : "=r"(a) : "l"(p));
    return a;
}
#define SWZ128(x) ((x) ^ (((x) >> 3) & 0x70))
__device__ __forceinline__ void cp16(uint32_t dst, const void* src) {
    asm volatile("cp.async.cg.shared.global [%0], [%1], 16;"
                 :: "r"(dst), "l"(src) : "memory");
}
__device__ __forceinline__ void ldsm4(uint32_t* r, uint32_t addr) {
    asm volatile("ldmatrix.sync.aligned.m8n8.x4.shared.b16 {%0,%1,%2,%3}, [%4];"
                 : "=r"(r[0]), "=r"(r[1]), "=r"(r[2]), "=r"(r[3]) : "r"(addr));
}
__device__ __forceinline__ void ldsm4t(uint32_t* r, uint32_t addr) {
    asm volatile("ldmatrix.sync.aligned.m8n8.x4.trans.shared.b16 {%0,%1,%2,%3}, [%4];"
                 : "=r"(r[0]), "=r"(r[1]), "=r"(r[2]), "=r"(r[3]) : "r"(addr));
}
__device__ __forceinline__ void mma16816(float* c, const uint32_t* a,
                                         uint32_t b0, uint32_t b1) {
    asm volatile(
        "mma.sync.aligned.m16n8k16.row.col.f32.f16.f16.f32 "
        "{%0,%1,%2,%3}, {%4,%5,%6,%7}, {%8,%9}, {%0,%1,%2,%3};"
        : "+f"(c[0]), "+f"(c[1]), "+f"(c[2]), "+f"(c[3])
        : "r"(a[0]), "r"(a[1]), "r"(a[2]), "r"(a[3]), "r"(b0), "r"(b1));
}

// Tile 128(o) x 128(l), K-chunk 64.
// Stage: A 128x128B (SW128) = 16KB ; B 64(k) x 256B (l-major) = 16KB => 32KB
#define STAGE_B   32768
#define B_OFF     16384
#define NSTAGE    3
#define GEMM_SMEM (NSTAGE * STAGE_B)   // 96 KB -> 2 CTAs/SM
#define GTHREADS  128

// B smem phys offset for (k, l): 256B rows, 16B-XOR swizzle within 128B seg
__device__ __forceinline__ uint32_t bswz(int k, int l) {
    return (uint32_t)(k * 256 + ((l >> 6) << 7) + (((l & 63) * 2) ^ ((k & 7) << 4)));
}

__device__ __forceinline__ void load_stage(uint32_t base, int kc, int tid,
                                           const __half* Ap, const __half* Bp) {
    int k0 = kc * 64;
    #pragma unroll
    for (int i = 0; i < 8; ++i) {          // A: 1024 x 16B
        int c = tid + (i << 7);
        int row = c >> 3, col = c & 7;
        cp16(base + SWZ128(row * 128 + col * 16),
             Ap + (size_t)row * CH + k0 + col * 8);
    }
    #pragma unroll
    for (int i = 0; i < 8; ++i) {          // B: 64 rows x 16 chunks of 16B
        int c = tid + (i << 7);
        int row = c >> 4, ch = c & 15;
        cp16(base + B_OFF + bswz(row, ch * 8),
             Bp + (size_t)(k0 + row) * Ld + ch * 8);
    }
    asm volatile("cp.async.commit_group;" ::: "memory");
}

// ---------------------------------------------------------------------------
// Kernel 4: fp16 HMMA GEMM + fused bias/GLU epilogue (R12/R14 config — the
// measured optimum: 128 threads, 4 warps of 64x64, tile 128x128, 3-stage
// pipeline, ONE __syncthreads per K-chunk, 2 CTAs/SM, no spills).
// Processes 4 batches starting at b0 (blockIdx.z 0..3).
// ---------------------------------------------------------------------------
__global__ void __launch_bounds__(GTHREADS, 2) gemm_hmma(const float* __restrict__ bias,
                                                         float* __restrict__ out,
                                                         int b0) {
    extern __shared__ char smem[];
    uint32_t sb = smem_u32(smem);
    const int tid = threadIdx.x, lane = tid & 31, wid = tid >> 5;
    const int b  = b0 + blockIdx.z;
    const int o0 = blockIdx.y * 128;       // permuted-M tile
    const int l0 = blockIdx.x * 128;
    const int wm = (wid & 1) * 64;         // 2 warp-rows of 64
    const int wn = (wid >> 1) * 64;        // 2 warp-cols of 64

    const __half* Ap = d_W_h + (size_t)o0 * CH;
    const __half* Bp = d_g_h + (size_t)b * CH * Ld + l0;

    float acc[4][8][4];
    #pragma unroll
    for (int mi = 0; mi < 4; ++mi)
        #pragma unroll
        for (int ni = 0; ni < 8; ++ni)
            #pragma unroll
            for (int v = 0; v < 4; ++v) acc[mi][ni][v] = 0.0f;

    load_stage(sb, 0, tid, Ap, Bp);
    load_stage(sb + STAGE_B, 1, tid, Ap, Bp);

    const int arow = (lane & 15);
    const int acol = (lane >> 4) << 4;
    const int bk = (lane & 7) + (lane & 8);
    const int bn = (lane & 16) >> 1;

    #pragma unroll 1
    for (int kc = 0; kc < 32; ++kc) {
        uint32_t base = sb + (kc % NSTAGE) * STAGE_B;
        if (kc <= 30) asm volatile("cp.async.wait_group 1;" ::: "memory");
        else          asm volatile("cp.async.wait_group 0;" ::: "memory");
        __syncthreads();
        // prefetch into stage (kc+2)%3 — consumed at kc-1, all warps past it
        if (kc + 2 < 32)
            load_stage(sb + ((kc + 2) % NSTAGE) * STAGE_B, kc + 2, tid, Ap, Bp);
        #pragma unroll
        for (int ks = 0; ks < 4; ++ks) {
            uint32_t a[4][4], bf[4][4];
            #pragma unroll
            for (int mi = 0; mi < 4; ++mi)
                ldsm4(a[mi], base + SWZ128((wm + mi * 16 + arow) * 128 +
                                           ks * 32 + acol));
            #pragma unroll
            for (int nj = 0; nj < 4; ++nj)
                ldsm4t(bf[nj], base + B_OFF + bswz(ks * 16 + bk,
                                                   wn + nj * 16 + bn));
            #pragma unroll
            for (int mi = 0; mi < 4; ++mi)
                #pragma unroll
                for (int ni = 0; ni < 8; ++ni)
                    mma16816(acc[mi][ni], a[mi],
                             bf[ni >> 1][(ni & 1) * 2],
                             bf[ni >> 1][(ni & 1) * 2 + 1]);
        }
    }

    // fused epilogue: a=c0,c1 (rows 0-7), gate=c2,c3 (rows 8-15), same h
    #pragma unroll
    for (int mi = 0; mi < 4; ++mi) {
        int g16 = (o0 + wm + mi * 16) >> 4;
        int h = g16 * 8 + (lane >> 2);
        float ba = bias[h];
        float bg = bias[h + Hd];
        float* orow = out + ((size_t)b * Hd + h) * Ld + l0 + wn;
        #pragma unroll
        for (int ni = 0; ni < 8; ++ni) {
            int lc = ni * 8 + (lane & 3) * 2;
            float a0 = acc[mi][ni][0] + ba;
            float a1 = acc[mi][ni][1] + ba;
            float g0 = acc[mi][ni][2] + bg;
            float g1 = acc[mi][ni][3] + bg;
            float2 v = make_float2(a0 / (1.0f + expf(-g0)),
                                   a1 / (1.0f + expf(-g1)));
            *reinterpret_cast<float2*>(orow + lc) = v;
        }
    }
}

// ---------------------------------------------------------------------------
extern "C" void kernel_launch(void* const* d_in, const int* in_sizes, int n_in,
                              void* d_out, int out_size) {
    const float* u    = (const float*)d_in[0];
    const float* kern = (const float*)d_in[1];
    const float* D    = (const float*)d_in[2];
    const float* Wout = (const float*)d_in[3];
    const float* bout = (const float*)d_in[4];
    float* out = (float*)d_out;

    // streams/events created ONCE on the first (correctness) call — before the
    // harness's pre-capture baseline — and reused afterwards. TWO side streams
    // total (the graph footprint proven safe in R10-R12/R14).
    static cudaStream_t s2 = nullptr, s3 = nullptr;
    static cudaEvent_t eS = nullptr, eW = nullptr, eF = nullptr, eC = nullptr,
                       eG1 = nullptr;
    if (!s2) {
        cudaStreamCreateWithFlags(&s2, cudaStreamNonBlocking);
        cudaStreamCreateWithFlags(&s3, cudaStreamNonBlocking);
        cudaEventCreateWithFlags(&eS,  cudaEventDisableTiming);
        cudaEventCreateWithFlags(&eW,  cudaEventDisableTiming);
        cudaEventCreateWithFlags(&eF,  cudaEventDisableTiming);
        cudaEventCreateWithFlags(&eC,  cudaEventDisableTiming);
        cudaEventCreateWithFlags(&eG1, cudaEventDisableTiming);
        cudaFuncSetAttribute(kf_fft_kernel,
            cudaFuncAttributeMaxDynamicSharedMemorySize, 2 * NF * (int)sizeof(float2));
        cudaFuncSetAttribute(conv_kernel,
            cudaFuncAttributeMaxDynamicSharedMemorySize, 3 * NF * (int)sizeof(float2));
        cudaFuncSetAttribute(gemm_hmma,
            cudaFuncAttributeMaxDynamicSharedMemorySize, GEMM_SMEM);
    }

    // DAG (3 streams total):
    //   0 : flag(eF) -> ew_half0 -> [eW,eC] gemm_half0 -> [eG1]
    //   s2: [eS] whalf(eW) -> [eF] ew_half1 -> [eC] gemm_half1(eG1)
    //   s3: [eF] kf_fft -> conv(eC)
    cudaEventRecord(eS, 0);
    cudaStreamWaitEvent(s2, eS, 0);
    whalf_kernel<<<(OUTD * CH / 8 + 255) / 256, 256, 0, s2>>>(Wout);
    cudaEventRecord(eW, s2);

    flag_kernel<<<CH, 256>>>(kern);
    cudaEventRecord(eF, 0);

    cudaStreamWaitEvent(s3, eF, 0);
    kf_fft_kernel<<<CH, 256, 2 * NF * sizeof(float2), s3>>>(kern);
    conv_kernel<<<296, 256, 3 * NF * sizeof(float2), s3>>>(u, D);
    cudaEventRecord(eC, s3);

    cudaStreamWaitEvent(s2, eF, 0);
    ew_kernel<<<4096, 256, 0, s2>>>(u, D, 4);          // batches 4-7
    cudaStreamWaitEvent(s2, eC, 0);
    gemm_hmma<<<dim3(Ld / 128, OUTD / 128, 4), GTHREADS, GEMM_SMEM, s2>>>(bout, out, 4);
    cudaEventRecord(eG1, s2);

    ew_kernel<<<4096, 256>>>(u, D, 0);                 // batches 0-3 (stream 0)

    cudaStreamWaitEvent(0, eW, 0);
    cudaStreamWaitEvent(0, eC, 0);
    gemm_hmma<<<dim3(Ld / 128, OUTD / 128, 4), GTHREADS, GEMM_SMEM>>>(bout, out, 0);

    cudaStreamWaitEvent(0, eG1, 0);
}

// round 17
// speedup vs baseline: 1.6603x; 1.0076x over previous
#include <cuda_runtime.h>
#include <cuda_bf16.h>
#include <cuda_fp16.h>
#include <math.h>
#include <stdint.h>

#define Bd   8
#define Hd   1024
#define Ld   2048
#define Cd   2
#define NF   4096      // FFT length = 2L
#define CH   2048      // C*H (GEMM K)
#define OUTD 2048      // 2H  (GEMM M, interleaved a/g rows)

// ---------------- scratch (static device globals; no runtime allocation) ----
__device__ float2 d_kf[(size_t)CH * NF];            // kernel spectra
__device__ int    d_kf_nz[CH];                      // per-row nonzero flags
__device__ __half d_g_h[(size_t)Bd * CH * Ld];      // post-GELU activations fp16 (k-major)
__device__ __half d_W_h[(size_t)OUTD * CH];         // W fp16, rows permuted for fused GLU

__device__ __forceinline__ float2 cmulf(float2 a, float2 b) {
    return make_float2(a.x * b.x - a.y * b.y, a.x * b.y + a.y * b.x);
}
// Fast erf (Abramowitz-Stegun 7.1.26, |err| <= 1.5e-7) — MUFU div/exp paths.
__device__ __forceinline__ float erf_fast(float x) {
    float ax = fabsf(x);
    float t = __fdividef(1.0f, fmaf(0.3275911f, ax, 1.0f));
    float p = t * fmaf(t, fmaf(t, fmaf(t, fmaf(t, 1.061405429f, -1.453152027f),
                                       1.421413741f), -0.284496736f), 0.254829592f);
    float r = 1.0f - p * __expf(-ax * ax);
    return copysignf(r, x);
}
__device__ __forceinline__ float gelu_f(float y) {
    return 0.5f * y * (1.0f + erf_fast(y * 0.70710678118654752f));
}

// ---------------------------------------------------------------------------
// Stockham radix-2 FFT, N=4096, 256 threads/block.
// ---------------------------------------------------------------------------
template<int SIGN>
__device__ void fft4096(float2* a, float2* b) {
    float2 *s = a, *d = b;
    int Ns = 1;
    #pragma unroll 1
    for (int stage = 0; stage < 12; ++stage) {
        __syncthreads();
        float wstep = (float)SIGN * 3.14159265358979323846f / (float)Ns;
        #pragma unroll
        for (int it = 0; it < 8; ++it) {
            int j = threadIdx.x + (it << 8);
            float2 v0 = s[j];
            float2 v1 = s[j + 2048];
            int jm = j & (Ns - 1);
            float ang = wstep * (float)jm;
            float sn, cs;
            __sincosf(ang, &sn, &cs);
            float2 t = make_float2(cs * v1.x - sn * v1.y,
                                   cs * v1.y + sn * v1.x);
            int idxD = 2 * j - jm;
            d[idxD]      = make_float2(v0.x + t.x, v0.y + t.y);
            d[idxD + Ns] = make_float2(v0.x - t.x, v0.y - t.y);
        }
        float2* tmp = s; s = d; d = tmp;
        Ns <<= 1;
    }
    __syncthreads();
}

// ---------------------------------------------------------------------------
// Kernel 0: flags only — any |kern[row][i]| > lam?  No smem FFT, fast.
// ---------------------------------------------------------------------------
__global__ void flag_kernel(const float* __restrict__ kern) {
    __shared__ int s_any;
    if (threadIdx.x == 0) s_any = 0;
    __syncthreads();
    int row = blockIdx.x;
    const float4* kr = reinterpret_cast<const float4*>(kern + (size_t)row * NF);
    int any = 0;
    #pragma unroll
    for (int i = 0; i < 4; ++i) {
        float4 v = kr[threadIdx.x + (i << 8)];
        any |= (fabsf(v.x) > 0.1f) | (fabsf(v.y) > 0.1f) |
               (fabsf(v.z) > 0.1f) | (fabsf(v.w) > 0.1f);
    }
    if (any) s_any = 1;
    __syncthreads();
    if (threadIdx.x == 0) d_kf_nz[row] = s_any;
}

// ---------------------------------------------------------------------------
// Kernel 1: FFT of soft-thresholded filter rows (only nonzero rows).
// ---------------------------------------------------------------------------
__global__ void kf_fft_kernel(const float* __restrict__ kern) {
    int row = blockIdx.x;
    if (!d_kf_nz[row]) return;
    extern __shared__ float2 sm[];
    float2* A  = sm;
    float2* Bf = sm + NF;
    const float* kr = kern + (size_t)row * NF;
    for (int i = threadIdx.x; i < NF; i += 256) {
        float v = kr[i];
        float t = fmaxf(fabsf(v) - 0.1f, 0.0f);
        A[i] = make_float2(copysignf(t, v), 0.0f);
    }
    fft4096<-1>(A, Bf);
    float2* out = d_kf + (size_t)row * NF;
    for (int i = threadIdx.x; i < NF; i += 256) out[i] = A[i];
}

// ---------------------------------------------------------------------------
// Kernel 2a: streaming fast path (both filter rows zero): gelu(u*D) -> fp16.
// Processes 4 batches starting at b0; 8 floats/thread.
// ---------------------------------------------------------------------------
__global__ void ew_kernel(const float* __restrict__ u,
                          const float* __restrict__ Dp, int b0) {
    int idx = blockIdx.x * blockDim.x + threadIdx.x;   // over 4*H*L/8 = 2^20
    int l8 = idx & (Ld / 8 - 1);
    int h  = (idx >> 8) & (Hd - 1);
    int b  = b0 + (idx >> 18);
    if (d_kf_nz[h] | d_kf_nz[Hd + h]) return;          // conv_kernel handles
    const float4* up = reinterpret_cast<const float4*>(
        u + ((size_t)b * Hd + h) * Ld + l8 * 8);
    float4 v0 = up[0], v1 = up[1];
    float D0 = Dp[h], D1 = Dp[Hd + h];
    uint4 o0, o1;
    {
        __half2 a = __floats2half2_rn(gelu_f(v0.x * D0), gelu_f(v0.y * D0));
        __half2 b2 = __floats2half2_rn(gelu_f(v0.z * D0), gelu_f(v0.w * D0));
        __half2 c = __floats2half2_rn(gelu_f(v1.x * D0), gelu_f(v1.y * D0));
        __half2 d = __floats2half2_rn(gelu_f(v1.z * D0), gelu_f(v1.w * D0));
        o0.x = *reinterpret_cast<uint32_t*>(&a);
        o0.y = *reinterpret_cast<uint32_t*>(&b2);
        o0.z = *reinterpret_cast<uint32_t*>(&c);
        o0.w = *reinterpret_cast<uint32_t*>(&d);
    }
    {
        __half2 a = __floats2half2_rn(gelu_f(v0.x * D1), gelu_f(v0.y * D1));
        __half2 b2 = __floats2half2_rn(gelu_f(v0.z * D1), gelu_f(v0.w * D1));
        __half2 c = __floats2half2_rn(gelu_f(v1.x * D1), gelu_f(v1.y * D1));
        __half2 d = __floats2half2_rn(gelu_f(v1.z * D1), gelu_f(v1.w * D1));
        o1.x = *reinterpret_cast<uint32_t*>(&a);
        o1.y = *reinterpret_cast<uint32_t*>(&b2);
        o1.z = *reinterpret_cast<uint32_t*>(&c);
        o1.w = *reinterpret_cast<uint32_t*>(&d);
    }
    *reinterpret_cast<uint4*>(d_g_h + ((size_t)b * CH + h) * Ld + l8 * 8) = o0;
    *reinterpret_cast<uint4*>(d_g_h + ((size_t)b * CH + Hd + h) * Ld + l8 * 8) = o1;
}

// ---------------------------------------------------------------------------
// Kernel 2b: FFT conv path — persistent grid; work only for nonzero rows.
// ---------------------------------------------------------------------------
__global__ void conv_kernel(const float* __restrict__ u,
                            const float* __restrict__ Dp) {
    extern __shared__ float2 sm[];
    float2* A  = sm;
    float2* Bf = sm + NF;
    float2* Uf = sm + 2 * NF;
    __half* stg = reinterpret_cast<__half*>(Bf);
    #pragma unroll 1
    for (int bh = blockIdx.x; bh < Bd * Hd; bh += gridDim.x) {
        int b = bh >> 10;
        int h = bh & (Hd - 1);
        int nz0 = d_kf_nz[h];
        int nz1 = d_kf_nz[Hd + h];
        if (!(nz0 | nz1)) continue;                    // ew_kernel handled
        __syncthreads();                               // smem reuse guard
        const float* ur = u + ((size_t)b * Hd + h) * Ld;
        float ul[8];
        #pragma unroll
        for (int it = 0; it < 8; ++it) {
            int l = threadIdx.x + (it << 8);
            float v = ur[l];
            ul[it] = v;
            A[l]      = make_float2(v, 0.0f);
            A[l + Ld] = make_float2(0.0f, 0.0f);
        }
        fft4096<-1>(A, Bf);
        for (int i = threadIdx.x; i < NF; i += 256) Uf[i] = A[i];
        __syncthreads();
        #pragma unroll 1
        for (int c = 0; c < Cd; ++c) {
            int nz = c ? nz1 : nz0;
            float Dch = Dp[c * Hd + h];
            __half* gr = d_g_h + ((size_t)b * CH + (size_t)c * Hd + h) * Ld;
            if (nz) {
                __syncthreads();
                const float2* kfr = d_kf + ((size_t)c * Hd + h) * NF;
                for (int i = threadIdx.x; i < NF; i += 256)
                    A[i] = cmulf(Uf[i], kfr[i]);
                fft4096<1>(A, Bf);
                #pragma unroll
                for (int it = 0; it < 8; ++it) {
                    int l = threadIdx.x + (it << 8);
                    float y = A[l].x * (1.0f / (float)NF) + ul[it] * Dch;
                    stg[l] = __float2half(gelu_f(y));
                }
            } else {
                __syncthreads();
                #pragma unroll
                for (int it = 0; it < 8; ++it) {
                    int l = threadIdx.x + (it << 8);
                    stg[l] = __float2half(gelu_f(ul[it] * Dch));
                }
            }
            __syncthreads();
            reinterpret_cast<uint4*>(gr)[threadIdx.x] =
                reinterpret_cast<const uint4*>(stg)[threadIdx.x];
        }
    }
}

// ---------------------------------------------------------------------------
// Kernel 3: W fp32 -> fp16 with GLU-fused row permutation, vectorized 8/thread.
// ---------------------------------------------------------------------------
__global__ void whalf_kernel(const float* __restrict__ W) {
    int idx = blockIdx.x * blockDim.x + threadIdx.x;   // over OUTD*CH/8
    if (idx >= OUTD * CH / 8) return;
    int r  = idx >> 8;                 // / (CH/8)
    int k8 = idx & (CH / 8 - 1);
    int grp = r >> 4, w = r & 15;
    int h = grp * 8 + (w & 7);
    int orig = (w < 8) ? h : h + Hd;
    const float4* src = reinterpret_cast<const float4*>(
        W + (size_t)orig * CH + k8 * 8);
    float4 v0 = src[0], v1 = src[1];
    __half2 h0 = __floats2half2_rn(v0.x, v0.y);
    __half2 h1 = __floats2half2_rn(v0.z, v0.w);
    __half2 h2 = __floats2half2_rn(v1.x, v1.y);
    __half2 h3 = __floats2half2_rn(v1.z, v1.w);
    uint4 o;
    o.x = *reinterpret_cast<uint32_t*>(&h0);
    o.y = *reinterpret_cast<uint32_t*>(&h1);
    o.z = *reinterpret_cast<uint32_t*>(&h2);
    o.w = *reinterpret_cast<uint32_t*>(&h3);
    *reinterpret_cast<uint4*>(d_W_h + (size_t)r * CH + k8 * 8) = o;
}

// ---------------------------------------------------------------------------
// HMMA GEMM helpers
// ---------------------------------------------------------------------------
__device__ __forceinline__ uint32_t smem_u32(const void* p) {
    uint32_t a;
    asm("{ .reg .u64 t; cvta.to.shared.u64 t, %1; cvt.u32.u64 %0, t; }"
        : "=r"(a) : "l"(p));
    return a;
}
#define SWZ128(x) ((x) ^ (((x) >> 3) & 0x70))
__device__ __forceinline__ void cp16(uint32_t dst, const void* src) {
    asm volatile("cp.async.cg.shared.global [%0], [%1], 16;"
                 :: "r"(dst), "l"(src) : "memory");
}
__device__ __forceinline__ void ldsm4(uint32_t* r, uint32_t addr) {
    asm volatile("ldmatrix.sync.aligned.m8n8.x4.shared.b16 {%0,%1,%2,%3}, [%4];"
                 : "=r"(r[0]), "=r"(r[1]), "=r"(r[2]), "=r"(r[3]) : "r"(addr));
}
__device__ __forceinline__ void ldsm4t(uint32_t* r, uint32_t addr) {
    asm volatile("ldmatrix.sync.aligned.m8n8.x4.trans.shared.b16 {%0,%1,%2,%3}, [%4];"
                 : "=r"(r[0]), "=r"(r[1]), "=r"(r[2]), "=r"(r[3]) : "r"(addr));
}
__device__ __forceinline__ void mma16816(float* c, const uint32_t* a,
                                         uint32_t b0, uint32_t b1) {
    asm volatile(
        "mma.sync.aligned.m16n8k16.row.col.f32.f16.f16.f32 "
        "{%0,%1,%2,%3}, {%4,%5,%6,%7}, {%8,%9}, {%0,%1,%2,%3};"
        : "+f"(c[0]), "+f"(c[1]), "+f"(c[2]), "+f"(c[3])
        : "r"(a[0]), "r"(a[1]), "r"(a[2]), "r"(a[3]), "r"(b0), "r"(b1));
}

// Tile 128(o) x 128(l), K-chunk 64.
// Stage: A 128x128B (SW128) = 16KB ; B 64(k) x 256B (l-major) = 16KB => 32KB
#define STAGE_B   32768
#define B_OFF     16384
#define NSTAGE    3
#define GEMM_SMEM (NSTAGE * STAGE_B)   // 96 KB -> 2 CTAs/SM
#define GTHREADS  128

// B smem phys offset for (k, l): 256B rows, 16B-XOR swizzle within 128B seg
__device__ __forceinline__ uint32_t bswz(int k, int l) {
    return (uint32_t)(k * 256 + ((l >> 6) << 7) + (((l & 63) * 2) ^ ((k & 7) << 4)));
}

__device__ __forceinline__ void load_stage(uint32_t base, int kc, int tid,
                                           const __half* Ap, const __half* Bp) {
    int k0 = kc * 64;
    #pragma unroll
    for (int i = 0; i < 8; ++i) {          // A: 1024 x 16B
        int c = tid + (i << 7);
        int row = c >> 3, col = c & 7;
        cp16(base + SWZ128(row * 128 + col * 16),
             Ap + (size_t)row * CH + k0 + col * 8);
    }
    #pragma unroll
    for (int i = 0; i < 8; ++i) {          // B: 64 rows x 16 chunks of 16B
        int c = tid + (i << 7);
        int row = c >> 4, ch = c & 15;
        cp16(base + B_OFF + bswz(row, ch * 8),
             Bp + (size_t)(k0 + row) * Ld + ch * 8);
    }
    asm volatile("cp.async.commit_group;" ::: "memory");
}

// ---------------------------------------------------------------------------
// Kernel 4: fp16 HMMA GEMM + fused bias/GLU epilogue (R12/R14 config — the
// measured optimum: 128 threads, 4 warps of 64x64, tile 128x128, 3-stage
// pipeline, ONE __syncthreads per K-chunk, 2 CTAs/SM, no spills).
// Processes 4 batches starting at b0 (blockIdx.z 0..3).
// ---------------------------------------------------------------------------
__global__ void __launch_bounds__(GTHREADS, 2) gemm_hmma(const float* __restrict__ bias,
                                                         float* __restrict__ out,
                                                         int b0) {
    extern __shared__ char smem[];
    uint32_t sb = smem_u32(smem);
    const int tid = threadIdx.x, lane = tid & 31, wid = tid >> 5;
    const int b  = b0 + blockIdx.z;
    const int o0 = blockIdx.y * 128;       // permuted-M tile
    const int l0 = blockIdx.x * 128;
    const int wm = (wid & 1) * 64;         // 2 warp-rows of 64
    const int wn = (wid >> 1) * 64;        // 2 warp-cols of 64

    const __half* Ap = d_W_h + (size_t)o0 * CH;
    const __half* Bp = d_g_h + (size_t)b * CH * Ld + l0;

    float acc[4][8][4];
    #pragma unroll
    for (int mi = 0; mi < 4; ++mi)
        #pragma unroll
        for (int ni = 0; ni < 8; ++ni)
            #pragma unroll
            for (int v = 0; v < 4; ++v) acc[mi][ni][v] = 0.0f;

    load_stage(sb, 0, tid, Ap, Bp);
    load_stage(sb + STAGE_B, 1, tid, Ap, Bp);

    const int arow = (lane & 15);
    const int acol = (lane >> 4) << 4;
    const int bk = (lane & 7) + (lane & 8);
    const int bn = (lane & 16) >> 1;

    #pragma unroll 1
    for (int kc = 0; kc < 32; ++kc) {
        uint32_t base = sb + (kc % NSTAGE) * STAGE_B;
        if (kc <= 30) asm volatile("cp.async.wait_group 1;" ::: "memory");
        else          asm volatile("cp.async.wait_group 0;" ::: "memory");
        __syncthreads();
        // prefetch into stage (kc+2)%3 — consumed at kc-1, all warps past it
        if (kc + 2 < 32)
            load_stage(sb + ((kc + 2) % NSTAGE) * STAGE_B, kc + 2, tid, Ap, Bp);
        #pragma unroll
        for (int ks = 0; ks < 4; ++ks) {
            uint32_t a[4][4], bf[4][4];
            #pragma unroll
            for (int mi = 0; mi < 4; ++mi)
                ldsm4(a[mi], base + SWZ128((wm + mi * 16 + arow) * 128 +
                                           ks * 32 + acol));
            #pragma unroll
            for (int nj = 0; nj < 4; ++nj)
                ldsm4t(bf[nj], base + B_OFF + bswz(ks * 16 + bk,
                                                   wn + nj * 16 + bn));
            #pragma unroll
            for (int mi = 0; mi < 4; ++mi)
                #pragma unroll
                for (int ni = 0; ni < 8; ++ni)
                    mma16816(acc[mi][ni], a[mi],
                             bf[ni >> 1][(ni & 1) * 2],
                             bf[ni >> 1][(ni & 1) * 2 + 1]);
        }
    }

    // fused epilogue: a=c0,c1 (rows 0-7), gate=c2,c3 (rows 8-15), same h
    #pragma unroll
    for (int mi = 0; mi < 4; ++mi) {
        int g16 = (o0 + wm + mi * 16) >> 4;
        int h = g16 * 8 + (lane >> 2);
        float ba = bias[h];
        float bg = bias[h + Hd];
        float* orow = out + ((size_t)b * Hd + h) * Ld + l0 + wn;
        #pragma unroll
        for (int ni = 0; ni < 8; ++ni) {
            int lc = ni * 8 + (lane & 3) * 2;
            float a0 = acc[mi][ni][0] + ba;
            float a1 = acc[mi][ni][1] + ba;
            float g0 = acc[mi][ni][2] + bg;
            float g1 = acc[mi][ni][3] + bg;
            float2 v = make_float2(a0 / (1.0f + expf(-g0)),
                                   a1 / (1.0f + expf(-g1)));
            *reinterpret_cast<float2*>(orow + lc) = v;
        }
    }
}

// ---------------------------------------------------------------------------
extern "C" void kernel_launch(void* const* d_in, const int* in_sizes, int n_in,
                              void* d_out, int out_size) {
    const float* u    = (const float*)d_in[0];
    const float* kern = (const float*)d_in[1];
    const float* D    = (const float*)d_in[2];
    const float* Wout = (const float*)d_in[3];
    const float* bout = (const float*)d_in[4];
    float* out = (float*)d_out;

    // streams/events created ONCE on the first (correctness) call — before the
    // harness's pre-capture baseline — and reused afterwards. TWO side streams
    // total (the graph footprint proven safe in R10-R12/R14/R16).
    static cudaStream_t s2 = nullptr, s3 = nullptr;
    static cudaEvent_t eS = nullptr, eW = nullptr, eF = nullptr, eC = nullptr,
                       eG1 = nullptr;
    if (!s2) {
        cudaStreamCreateWithFlags(&s2, cudaStreamNonBlocking);
        cudaStreamCreateWithFlags(&s3, cudaStreamNonBlocking);
        cudaEventCreateWithFlags(&eS,  cudaEventDisableTiming);
        cudaEventCreateWithFlags(&eW,  cudaEventDisableTiming);
        cudaEventCreateWithFlags(&eF,  cudaEventDisableTiming);
        cudaEventCreateWithFlags(&eC,  cudaEventDisableTiming);
        cudaEventCreateWithFlags(&eG1, cudaEventDisableTiming);
        cudaFuncSetAttribute(kf_fft_kernel,
            cudaFuncAttributeMaxDynamicSharedMemorySize, 2 * NF * (int)sizeof(float2));
        cudaFuncSetAttribute(conv_kernel,
            cudaFuncAttributeMaxDynamicSharedMemorySize, 3 * NF * (int)sizeof(float2));
        cudaFuncSetAttribute(gemm_hmma,
            cudaFuncAttributeMaxDynamicSharedMemorySize, GEMM_SMEM);
    }

    // DAG (3 streams total):
    //   0 : flag(eF) -> ew_half0 -> [eW,eC] gemm_half0 -> [eG1]
    //   s2: [eS] whalf(eW) -> [eF] ew_half1 -> [eC] gemm_half1(eG1)
    //   s3: [eF] kf_fft -> conv(eC)
    cudaEventRecord(eS, 0);
    cudaStreamWaitEvent(s2, eS, 0);
    whalf_kernel<<<(OUTD * CH / 8 + 255) / 256, 256, 0, s2>>>(Wout);
    cudaEventRecord(eW, s2);

    flag_kernel<<<CH, 256>>>(kern);
    cudaEventRecord(eF, 0);

    cudaStreamWaitEvent(s3, eF, 0);
    kf_fft_kernel<<<CH, 256, 2 * NF * sizeof(float2), s3>>>(kern);
    conv_kernel<<<296, 256, 3 * NF * sizeof(float2), s3>>>(u, D);
    cudaEventRecord(eC, s3);

    cudaStreamWaitEvent(s2, eF, 0);
    ew_kernel<<<4096, 256, 0, s2>>>(u, D, 4);          // batches 4-7
    cudaStreamWaitEvent(s2, eC, 0);
    gemm_hmma<<<dim3(Ld / 128, OUTD / 128, 4), GTHREADS, GEMM_SMEM, s2>>>(bout, out, 4);
    cudaEventRecord(eG1, s2);

    ew_kernel<<<4096, 256>>>(u, D, 0);                 // batches 0-3 (stream 0)

    cudaStreamWaitEvent(0, eW, 0);
    cudaStreamWaitEvent(0, eC, 0);
    gemm_hmma<<<dim3(Ld / 128, OUTD / 128, 4), GTHREADS, GEMM_SMEM>>>(bout, out, 0);

    cudaStreamWaitEvent(0, eG1, 0);
}